// round 4
// baseline (speedup 1.0000x reference)
#include <cuda_runtime.h>

#define TPB 128
#define ROW 63            // 21 joints * 3
#define NV4 (TPB*ROW/4)   // 2016 float4 per block

__global__ void __launch_bounds__(TPB, 5)
kin_kernel(const float* __restrict__ joints,
           const float* __restrict__ tempJ,
           float* __restrict__ out, int n)
{
    __shared__ __align__(16) float sm[TPB * ROW];   // 32256 B, reused 3x
    __shared__ float sblen[TPB * 15];               // 7680 B, stride 15 (odd) = conflict-free
    const int tid = threadIdx.x;
    const long long total = (long long)n * ROW;
    const long long gbase = (long long)blockIdx.x * (TPB * ROW);
    const bool full = (gbase + TPB * ROW) <= total;
    const bool active = ((long long)blockIdx.x * TPB + tid) < n;
    const int base = tid * ROW;
    const int bbase = tid * 15;

    const int PALM5[5] = {1, 4, 7, 10, 13};
    const int CH[15] = {2,3,17, 5,6,18, 8,9,20, 11,12,19, 14,15,16};
    const int PA[15] = {1,2,3, 4,5,6, 7,8,9, 10,11,12, 13,14,15};

    // ================= stage tempJ (coalesced float4) =================
    if (full) {
        #pragma unroll
        for (int i = 0; i < 16; ++i) {
            int q = i * TPB + tid;
            if (q < NV4)
                reinterpret_cast<float4*>(sm)[q] =
                    reinterpret_cast<const float4*>(tempJ + gbase)[q];
        }
    } else {
        for (int q = tid; q < TPB * ROW; q += TPB) {
            long long g = gbase + q;
            if (g < total) sm[q] = tempJ[g];
        }
    }
    __syncthreads();

    // extract from template: centered palm points (regs) + bone lengths (smem)
    float sp[5][3];
    if (active) {
        const float t0x = sm[base + 0], t0y = sm[base + 1], t0z = sm[base + 2];
        #pragma unroll
        for (int p = 0; p < 5; ++p) {
            sp[p][0] = sm[base + 3 * PALM5[p] + 0] - t0x;
            sp[p][1] = sm[base + 3 * PALM5[p] + 1] - t0y;
            sp[p][2] = sm[base + 3 * PALM5[p] + 2] - t0z;
        }
        #pragma unroll
        for (int i = 0; i < 15; ++i) {
            float bx = sm[base + 3*CH[i] + 0] - sm[base + 3*PA[i] + 0];
            float by = sm[base + 3*CH[i] + 1] - sm[base + 3*PA[i] + 1];
            float bz = sm[base + 3*CH[i] + 2] - sm[base + 3*PA[i] + 2];
            sblen[bbase + i] = sqrtf(bx*bx + by*by + bz*bz);
        }
    }
    __syncthreads();

    // ================= stage joints (overwrite same buffer) =================
    if (full) {
        #pragma unroll
        for (int i = 0; i < 16; ++i) {
            int q = i * TPB + tid;
            if (q < NV4)
                reinterpret_cast<float4*>(sm)[q] =
                    reinterpret_cast<const float4*>(joints + gbase)[q];
        }
    } else {
        for (int q = tid; q < TPB * ROW; q += TPB) {
            long long g = gbase + q;
            if (g < total) sm[q] = joints[g];
        }
    }
    __syncthreads();

    if (active) {
        const float wx = sm[base + 0], wy = sm[base + 1], wz = sm[base + 2];

        // ---- H = sum_palm src ⊗ dst ----
        float H[3][3] = {{0,0,0},{0,0,0},{0,0,0}};
        #pragma unroll
        for (int p = 0; p < 5; ++p) {
            float jx = sm[base + 3 * PALM5[p] + 0] - wx;
            float jy = sm[base + 3 * PALM5[p] + 1] - wy;
            float jz = sm[base + 3 * PALM5[p] + 2] - wz;
            H[0][0] += sp[p][0]*jx; H[0][1] += sp[p][0]*jy; H[0][2] += sp[p][0]*jz;
            H[1][0] += sp[p][1]*jx; H[1][1] += sp[p][1]*jy; H[1][2] += sp[p][1]*jz;
            H[2][0] += sp[p][2]*jx; H[2][1] += sp[p][2]*jy; H[2][2] += sp[p][2]*jz;
        }

        // ---- A = H^T H ; 4-sweep branchless cyclic Jacobi ----
        float A[3][3];
        #pragma unroll
        for (int a = 0; a < 3; ++a)
            #pragma unroll
            for (int b = 0; b < 3; ++b)
                A[a][b] = H[0][a]*H[0][b] + H[1][a]*H[1][b] + H[2][a]*H[2][b];

        float V[3][3] = {{1,0,0},{0,1,0},{0,0,1}};
        #pragma unroll
        for (int sweep = 0; sweep < 4; ++sweep) {
            #pragma unroll
            for (int pair = 0; pair < 3; ++pair) {
                const int p = (pair == 2) ? 1 : 0;
                const int q = (pair == 0) ? 1 : 2;
                const int r = 3 - p - q;
                float apq = A[p][q];
                float den = 2.0f * apq;
                // sign-guarded: apq==0 -> tau huge/0 -> consistent no-op/valid rotation
                float tau = (A[q][q] - A[p][p]) / (den + copysignf(1e-30f, den));
                float t = 1.0f / (fabsf(tau) + sqrtf(1.0f + tau * tau));
                t = copysignf(t, tau);
                float c = rsqrtf(1.0f + t * t);
                float s = t * c;
                A[p][p] -= t * apq;
                A[q][q] += t * apq;
                A[p][q] = 0.f; A[q][p] = 0.f;
                float arp = A[r][p], arq = A[r][q];
                A[r][p] = c * arp - s * arq; A[p][r] = A[r][p];
                A[r][q] = s * arp + c * arq; A[q][r] = A[r][q];
                #pragma unroll
                for (int k = 0; k < 3; ++k) {
                    float vp = V[k][p], vq = V[k][q];
                    V[k][p] = c * vp - s * vq;
                    V[k][q] = s * vp + c * vq;
                }
            }
        }

        // sort eigenvalues (descending) -> v1, v2; v3 = v1 x v2
        float e0 = A[0][0], e1 = A[1][1], e2 = A[2][2];
        int i0 = 0; float em = e0;
        if (e1 > em) { i0 = 1; em = e1; }
        if (e2 > em) { i0 = 2; em = e2; }
        const int a1 = (i0 + 1) % 3, b1 = (i0 + 2) % 3;
        float ea = (a1 == 0) ? e0 : (a1 == 1) ? e1 : e2;
        float eb = (b1 == 0) ? e0 : (b1 == 1) ? e1 : e2;
        const int i1 = (ea >= eb) ? a1 : b1;

        float v1[3], v2[3], v3[3];
        #pragma unroll
        for (int k = 0; k < 3; ++k) {
            v1[k] = (i0 == 0) ? V[k][0] : (i0 == 1) ? V[k][1] : V[k][2];
            v2[k] = (i1 == 0) ? V[k][0] : (i1 == 1) ? V[k][1] : V[k][2];
        }
        v3[0] = v1[1]*v2[2] - v1[2]*v2[1];
        v3[1] = v1[2]*v2[0] - v1[0]*v2[2];
        v3[2] = v1[0]*v2[1] - v1[1]*v2[0];

        // u1 = norm(H v1); u2 = norm(GS(H v2)); u3 = u1 x u2
        float u1[3], u2[3], u3[3];
        #pragma unroll
        for (int k = 0; k < 3; ++k)
            u1[k] = H[k][0]*v1[0] + H[k][1]*v1[1] + H[k][2]*v1[2];
        {
            float inv = rsqrtf(u1[0]*u1[0] + u1[1]*u1[1] + u1[2]*u1[2] + 1e-30f);
            u1[0] *= inv; u1[1] *= inv; u1[2] *= inv;
        }
        #pragma unroll
        for (int k = 0; k < 3; ++k)
            u2[k] = H[k][0]*v2[0] + H[k][1]*v2[1] + H[k][2]*v2[2];
        {
            float pr = u1[0]*u2[0] + u1[1]*u2[1] + u1[2]*u2[2];
            u2[0] -= pr * u1[0]; u2[1] -= pr * u1[1]; u2[2] -= pr * u1[2];
            float inv = rsqrtf(u2[0]*u2[0] + u2[1]*u2[1] + u2[2]*u2[2] + 1e-30f);
            u2[0] *= inv; u2[1] *= inv; u2[2] *= inv;
        }
        u3[0] = u1[1]*u2[2] - u1[2]*u2[1];
        u3[1] = u1[2]*u2[0] - u1[0]*u2[2];
        u3[2] = u1[0]*u2[1] - u1[1]*u2[0];

        // R = v1 u1^T + v2 u2^T + v3 u3^T
        float R[3][3];
        #pragma unroll
        for (int a = 0; a < 3; ++a)
            #pragma unroll
            for (int b = 0; b < 3; ++b)
                R[a][b] = v1[a]*u1[b] + v2[a]*u2[b] + v3[a]*u3[b];

        // ---- rotate template palm points, write palm outputs in place ----
        #pragma unroll
        for (int p = 0; p < 5; ++p) {
            float tx = R[0][0]*sp[p][0] + R[0][1]*sp[p][1] + R[0][2]*sp[p][2];
            float ty = R[1][0]*sp[p][0] + R[1][1]*sp[p][1] + R[1][2]*sp[p][2];
            float tz = R[2][0]*sp[p][0] + R[2][1]*sp[p][1] + R[2][2]*sp[p][2];
            sm[base + 3*PALM5[p] + 0] = tx + wx;
            sm[base + 3*PALM5[p] + 1] = ty + wy;
            sm[base + 3*PALM5[p] + 2] = tz + wz;
        }
        // wrist slot already holds w (T[0] = 0)

        // ---- kinematic chain, finger-major; rolling (gpT, paT) ----
        #pragma unroll
        for (int f = 0; f < 5; ++f) {
            float gx = 0.f, gy = 0.f, gz = 0.f;
            float px = sm[base + 3*PALM5[f] + 0] - wx;   // finger base (palm output)
            float py = sm[base + 3*PALM5[f] + 1] - wy;
            float pz = sm[base + 3*PALM5[f] + 2] - wz;
            #pragma unroll
            for (int k = 0; k < 3; ++k) {
                const int i = 3 * f + k;
                const int ch = CH[i];

                float v1x = (sm[base + 3*ch + 0] - wx) - px;
                float v1y = (sm[base + 3*ch + 1] - wy) - py;
                float v1z = (sm[base + 3*ch + 2] - wz) - pz;
                float d2  = v1x*v1x + v1y*v1y + v1z*v1z;
                float scl = sblen[bbase + i] * rsqrtf(d2 + 1e-24f);
                float vbx = v1x * scl, vby = v1y * scl, vbz = v1z * scl;

                // branchless flex clamp: angle(v0, vb) clipped to [0, pi/2]
                float v0x = px - gx, v0y = py - gy, v0z = pz - gz;
                float crx = v0y*vbz - v0z*vby;
                float cry = v0z*vbx - v0x*vbz;
                float crz = v0x*vby - v0y*vbx;
                float cdot = v0x*vbx + v0y*vby + v0z*vbz;

                float s2   = crx*crx + cry*cry + crz*crz;
                float sN   = sqrtf(s2);
                float rinv = rsqrtf(s2 + cdot*cdot + 1e-30f);
                bool  flex = (cdot < 0.0f);
                float cd = flex ? sN * rinv   : 1.0f;   // cos(delta)
                float sd = flex ? cdot * rinv : 0.0f;   // sin(delta) (<=0)
                float ainv = rsqrtf(s2 + 1e-30f);
                float ax = crx * ainv, ay = cry * ainv, az = crz * ainv;
                float adv = ax*vbx + ay*vby + az*vbz;
                float om  = (1.0f - cd) * adv;
                float cavx = ay*vbz - az*vby;
                float cavy = az*vbx - ax*vbz;
                float cavz = ax*vby - ay*vbx;
                float nx = vbx*cd + cavx*sd + ax*om;
                float ny = vby*cd + cavy*sd + ay*om;
                float nz = vbz*cd + cavz*sd + az*om;

                float cx = px + nx, cy = py + ny, cz = pz + nz;

                // child's raw joint value is dead now -> write output in place
                sm[base + 3*ch + 0] = cx + wx;
                sm[base + 3*ch + 1] = cy + wy;
                sm[base + 3*ch + 2] = cz + wz;

                gx = px; gy = py; gz = pz;
                px = cx; py = cy; pz = cz;
            }
        }
    }
    __syncthreads();

    // ================= coalesced float4 store =================
    if (full) {
        #pragma unroll
        for (int i = 0; i < 16; ++i) {
            int q = i * TPB + tid;
            if (q < NV4)
                reinterpret_cast<float4*>(out + gbase)[q] =
                    reinterpret_cast<const float4*>(sm)[q];
        }
    } else {
        for (int q = tid; q < TPB * ROW; q += TPB) {
            long long g = gbase + q;
            if (g < total) out[g] = sm[q];
        }
    }
}

extern "C" void kernel_launch(void* const* d_in, const int* in_sizes, int n_in,
                              void* d_out, int out_size)
{
    const float* joints = (const float*)d_in[0];
    const float* tempJ  = (const float*)d_in[1];
    float* out = (float*)d_out;
    const int n = in_sizes[0] / ROW;     // 131072
    const int blocks = (n + TPB - 1) / TPB;
    kin_kernel<<<blocks, TPB>>>(joints, tempJ, out, n);
}

// round 8
// speedup vs baseline: 1.3253x; 1.3253x over previous
#include <cuda_runtime.h>

#define TPB 128
#define ROW 63            // 21 joints * 3
#define NV4 (TPB*ROW/4)   // 2016 float4 per block

// fast sqrt via MUFU.RSQ (no Newton tail); eps keeps 0 -> 0
__device__ __forceinline__ float fsqrt_fast(float x) {
    return x * rsqrtf(x + 1e-30f);
}

__global__ void __launch_bounds__(TPB, 5)
kin_kernel(const float* __restrict__ joints,
           const float* __restrict__ tempJ,
           float* __restrict__ out, int n)
{
    __shared__ __align__(16) float sm[TPB * ROW];   // 32256 B, reused 3x
    __shared__ float sblen[TPB * 15];               // stride 15 (odd) = conflict-free
    const int tid = threadIdx.x;
    const long long total = (long long)n * ROW;
    const long long gbase = (long long)blockIdx.x * (TPB * ROW);
    const bool full = (gbase + TPB * ROW) <= total;
    const bool active = ((long long)blockIdx.x * TPB + tid) < n;
    const int base = tid * ROW;
    const int bbase = tid * 15;

    const int PALM5[5] = {1, 4, 7, 10, 13};
    const int CH[15] = {2,3,17, 5,6,18, 8,9,20, 11,12,19, 14,15,16};
    const int PA[15] = {1,2,3, 4,5,6, 7,8,9, 10,11,12, 13,14,15};

    // ================= stage tempJ (coalesced float4) =================
    if (full) {
        #pragma unroll
        for (int i = 0; i < 16; ++i) {
            int q = i * TPB + tid;
            if (q < NV4)
                reinterpret_cast<float4*>(sm)[q] =
                    reinterpret_cast<const float4*>(tempJ + gbase)[q];
        }
    } else {
        for (int q = tid; q < TPB * ROW; q += TPB) {
            long long g = gbase + q;
            if (g < total) sm[q] = tempJ[g];
        }
    }
    __syncthreads();

    // extract from template: centered palm points (regs) + bone lengths (smem)
    float sp[5][3];
    if (active) {
        const float t0x = sm[base + 0], t0y = sm[base + 1], t0z = sm[base + 2];
        #pragma unroll
        for (int p = 0; p < 5; ++p) {
            sp[p][0] = sm[base + 3 * PALM5[p] + 0] - t0x;
            sp[p][1] = sm[base + 3 * PALM5[p] + 1] - t0y;
            sp[p][2] = sm[base + 3 * PALM5[p] + 2] - t0z;
        }
        #pragma unroll
        for (int i = 0; i < 15; ++i) {
            float bx = sm[base + 3*CH[i] + 0] - sm[base + 3*PA[i] + 0];
            float by = sm[base + 3*CH[i] + 1] - sm[base + 3*PA[i] + 1];
            float bz = sm[base + 3*CH[i] + 2] - sm[base + 3*PA[i] + 2];
            sblen[bbase + i] = fsqrt_fast(bx*bx + by*by + bz*bz);
        }
    }
    __syncthreads();

    // ================= stage joints (overwrite same buffer) =================
    if (full) {
        #pragma unroll
        for (int i = 0; i < 16; ++i) {
            int q = i * TPB + tid;
            if (q < NV4)
                reinterpret_cast<float4*>(sm)[q] =
                    reinterpret_cast<const float4*>(joints + gbase)[q];
        }
    } else {
        for (int q = tid; q < TPB * ROW; q += TPB) {
            long long g = gbase + q;
            if (g < total) sm[q] = joints[g];
        }
    }
    __syncthreads();

    if (active) {
        const float wx = sm[base + 0], wy = sm[base + 1], wz = sm[base + 2];

        // ---- H = sum_palm src ⊗ dst ----
        float H[3][3] = {{0,0,0},{0,0,0},{0,0,0}};
        #pragma unroll
        for (int p = 0; p < 5; ++p) {
            float jx = sm[base + 3 * PALM5[p] + 0] - wx;
            float jy = sm[base + 3 * PALM5[p] + 1] - wy;
            float jz = sm[base + 3 * PALM5[p] + 2] - wz;
            H[0][0] += sp[p][0]*jx; H[0][1] += sp[p][0]*jy; H[0][2] += sp[p][0]*jz;
            H[1][0] += sp[p][1]*jx; H[1][1] += sp[p][1]*jy; H[1][2] += sp[p][1]*jz;
            H[2][0] += sp[p][2]*jx; H[2][1] += sp[p][2]*jy; H[2][2] += sp[p][2]*jz;
        }

        // ---- A = H^T H ; 3-sweep division-free cyclic Jacobi ----
        float A[3][3];
        #pragma unroll
        for (int a = 0; a < 3; ++a)
            #pragma unroll
            for (int b = 0; b < 3; ++b)
                A[a][b] = H[0][a]*H[0][b] + H[1][a]*H[1][b] + H[2][a]*H[2][b];

        float V[3][3] = {{1,0,0},{0,1,0},{0,0,1}};
        #pragma unroll
        for (int sweep = 0; sweep < 3; ++sweep) {
            #pragma unroll
            for (int pair = 0; pair < 3; ++pair) {
                const int p = (pair == 2) ? 1 : 0;
                const int q = (pair == 0) ? 1 : 2;
                const int r = 3 - p - q;
                float apq = A[p][q];
                float x = 0.5f * (A[q][q] - A[p][p]);
                // inner rotation annihilating apq: tan(2θ) = apq/x, |θ| <= 45°
                float rinv = rsqrtf(x*x + apq*apq + 1e-36f);
                float co = (fabsf(x) + 1e-18f) * rinv;        // cos2θ (>=0)
                float si = apq * copysignf(1.0f, x) * rinv;   // sin2θ = apq·sign(x)/r
                float h  = 0.5f + 0.5f * co;                  // c²
                float cinv = rsqrtf(h);                       // 1/c
                float c = h * cinv;
                float s = 0.5f * si * cinv;
                float t = s * cinv;                           // tanθ
                A[p][p] -= t * apq;
                A[q][q] += t * apq;
                A[p][q] = 0.f; A[q][p] = 0.f;
                float arp = A[r][p], arq = A[r][q];
                A[r][p] = c * arp - s * arq; A[p][r] = A[r][p];
                A[r][q] = s * arp + c * arq; A[q][r] = A[r][q];
                #pragma unroll
                for (int k = 0; k < 3; ++k) {
                    float vp = V[k][p], vq = V[k][q];
                    V[k][p] = c * vp - s * vq;
                    V[k][q] = s * vp + c * vq;
                }
            }
        }

        // sort eigenvalues (descending) -> v1, v2; v3 = v1 x v2
        float e0 = A[0][0], e1 = A[1][1], e2 = A[2][2];
        int i0 = 0; float em = e0;
        if (e1 > em) { i0 = 1; em = e1; }
        if (e2 > em) { i0 = 2; em = e2; }
        const int a1 = (i0 + 1) % 3, b1 = (i0 + 2) % 3;
        float ea = (a1 == 0) ? e0 : (a1 == 1) ? e1 : e2;
        float eb = (b1 == 0) ? e0 : (b1 == 1) ? e1 : e2;
        const int i1 = (ea >= eb) ? a1 : b1;

        float v1[3], v2[3], v3[3];
        #pragma unroll
        for (int k = 0; k < 3; ++k) {
            v1[k] = (i0 == 0) ? V[k][0] : (i0 == 1) ? V[k][1] : V[k][2];
            v2[k] = (i1 == 0) ? V[k][0] : (i1 == 1) ? V[k][1] : V[k][2];
        }
        v3[0] = v1[1]*v2[2] - v1[2]*v2[1];
        v3[1] = v1[2]*v2[0] - v1[0]*v2[2];
        v3[2] = v1[0]*v2[1] - v1[1]*v2[0];

        // u1 = norm(H v1); u2 = norm(GS(H v2)); u3 = u1 x u2
        float u1[3], u2[3], u3[3];
        #pragma unroll
        for (int k = 0; k < 3; ++k)
            u1[k] = H[k][0]*v1[0] + H[k][1]*v1[1] + H[k][2]*v1[2];
        {
            float inv = rsqrtf(u1[0]*u1[0] + u1[1]*u1[1] + u1[2]*u1[2] + 1e-30f);
            u1[0] *= inv; u1[1] *= inv; u1[2] *= inv;
        }
        #pragma unroll
        for (int k = 0; k < 3; ++k)
            u2[k] = H[k][0]*v2[0] + H[k][1]*v2[1] + H[k][2]*v2[2];
        {
            float pr = u1[0]*u2[0] + u1[1]*u2[1] + u1[2]*u2[2];
            u2[0] -= pr * u1[0]; u2[1] -= pr * u1[1]; u2[2] -= pr * u1[2];
            float inv = rsqrtf(u2[0]*u2[0] + u2[1]*u2[1] + u2[2]*u2[2] + 1e-30f);
            u2[0] *= inv; u2[1] *= inv; u2[2] *= inv;
        }
        u3[0] = u1[1]*u2[2] - u1[2]*u2[1];
        u3[1] = u1[2]*u2[0] - u1[0]*u2[2];
        u3[2] = u1[0]*u2[1] - u1[1]*u2[0];

        // R = v1 u1^T + v2 u2^T + v3 u3^T
        float R[3][3];
        #pragma unroll
        for (int a = 0; a < 3; ++a)
            #pragma unroll
            for (int b = 0; b < 3; ++b)
                R[a][b] = v1[a]*u1[b] + v2[a]*u2[b] + v3[a]*u3[b];

        // ---- rotate template palm points, write palm outputs in place ----
        #pragma unroll
        for (int p = 0; p < 5; ++p) {
            float tx = R[0][0]*sp[p][0] + R[0][1]*sp[p][1] + R[0][2]*sp[p][2];
            float ty = R[1][0]*sp[p][0] + R[1][1]*sp[p][1] + R[1][2]*sp[p][2];
            float tz = R[2][0]*sp[p][0] + R[2][1]*sp[p][1] + R[2][2]*sp[p][2];
            sm[base + 3*PALM5[p] + 0] = tx + wx;
            sm[base + 3*PALM5[p] + 1] = ty + wy;
            sm[base + 3*PALM5[p] + 2] = tz + wz;
        }
        // wrist slot already holds w (T[0] = 0)

        // ---- kinematic chain, finger-major; rolling (gpT, paT) ----
        #pragma unroll
        for (int f = 0; f < 5; ++f) {
            float gx = 0.f, gy = 0.f, gz = 0.f;
            float px = sm[base + 3*PALM5[f] + 0] - wx;
            float py = sm[base + 3*PALM5[f] + 1] - wy;
            float pz = sm[base + 3*PALM5[f] + 2] - wz;
            #pragma unroll
            for (int k = 0; k < 3; ++k) {
                const int i = 3 * f + k;
                const int ch = CH[i];

                float v1x = (sm[base + 3*ch + 0] - wx) - px;
                float v1y = (sm[base + 3*ch + 1] - wy) - py;
                float v1z = (sm[base + 3*ch + 2] - wz) - pz;
                float d2  = v1x*v1x + v1y*v1y + v1z*v1z;
                float scl = sblen[bbase + i] * rsqrtf(d2 + 1e-24f);
                float vbx = v1x * scl, vby = v1y * scl, vbz = v1z * scl;

                // branchless flex clamp: angle(v0, vb) clipped to [0, pi/2]
                float v0x = px - gx, v0y = py - gy, v0z = pz - gz;
                float crx = v0y*vbz - v0z*vby;
                float cry = v0z*vbx - v0x*vbz;
                float crz = v0x*vby - v0y*vbx;
                float cdot = v0x*vbx + v0y*vby + v0z*vbz;

                float s2   = crx*crx + cry*cry + crz*crz;
                float ainv = rsqrtf(s2 + 1e-30f);            // 1/|cr|
                float sN   = s2 * ainv;                      // |cr|
                float rinv = rsqrtf(s2 + cdot*cdot + 1e-30f);
                bool  flex = (cdot < 0.0f);
                float cd = flex ? sN * rinv   : 1.0f;        // cos(delta)
                float sd = flex ? cdot * rinv : 0.0f;        // sin(delta) (<=0)
                float ax = crx * ainv, ay = cry * ainv, az = crz * ainv;
                float adv = ax*vbx + ay*vby + az*vbz;
                float om  = (1.0f - cd) * adv;
                float cavx = ay*vbz - az*vby;
                float cavy = az*vbx - ax*vbz;
                float cavz = ax*vby - ay*vbx;
                float nx = vbx*cd + cavx*sd + ax*om;
                float ny = vby*cd + cavy*sd + ay*om;
                float nz = vbz*cd + cavz*sd + az*om;

                float cx = px + nx, cy = py + ny, cz = pz + nz;

                // child's raw joint value is dead now -> write output in place
                sm[base + 3*ch + 0] = cx + wx;
                sm[base + 3*ch + 1] = cy + wy;
                sm[base + 3*ch + 2] = cz + wz;

                gx = px; gy = py; gz = pz;
                px = cx; py = cy; pz = cz;
            }
        }
    }
    __syncthreads();

    // ================= coalesced float4 store =================
    if (full) {
        #pragma unroll
        for (int i = 0; i < 16; ++i) {
            int q = i * TPB + tid;
            if (q < NV4)
                reinterpret_cast<float4*>(out + gbase)[q] =
                    reinterpret_cast<const float4*>(sm)[q];
        }
    } else {
        for (int q = tid; q < TPB * ROW; q += TPB) {
            long long g = gbase + q;
            if (g < total) out[g] = sm[q];
        }
    }
}

extern "C" void kernel_launch(void* const* d_in, const int* in_sizes, int n_in,
                              void* d_out, int out_size)
{
    const float* joints = (const float*)d_in[0];
    const float* tempJ  = (const float*)d_in[1];
    float* out = (float*)d_out;
    const int n = in_sizes[0] / ROW;     // 131072
    const int blocks = (n + TPB - 1) / TPB;
    kin_kernel<<<blocks, TPB>>>(joints, tempJ, out, n);
}

// round 9
// speedup vs baseline: 1.4451x; 1.0904x over previous
#include <cuda_runtime.h>

#define TPB 128
#define ROW 63            // 21 joints * 3
#define NV4 (TPB*ROW/4)   // 2016 float4 per block

// fast sqrt via MUFU.RSQ (no Newton tail); eps keeps 0 -> 0
__device__ __forceinline__ float fsqrt_fast(float x) {
    return x * rsqrtf(x + 1e-30f);
}

__global__ void __launch_bounds__(TPB, 5)
kin_kernel(const float* __restrict__ joints,
           const float* __restrict__ tempJ,
           float* __restrict__ out, int n)
{
    __shared__ __align__(16) float sm[TPB * ROW];   // 32256 B, reused 3x
    __shared__ float sblen[TPB * 15];               // stride 15 (odd) = conflict-free
    const int tid = threadIdx.x;
    const long long total = (long long)n * ROW;
    const long long gbase = (long long)blockIdx.x * (TPB * ROW);
    const bool full = (gbase + TPB * ROW) <= total;
    const bool active = ((long long)blockIdx.x * TPB + tid) < n;
    const int base = tid * ROW;
    const int bbase = tid * 15;

    const int PALM5[5] = {1, 4, 7, 10, 13};
    const int CH[15] = {2,3,17, 5,6,18, 8,9,20, 11,12,19, 14,15,16};
    const int PA[15] = {1,2,3, 4,5,6, 7,8,9, 10,11,12, 13,14,15};

    // ================= stage tempJ (coalesced float4) =================
    if (full) {
        #pragma unroll
        for (int i = 0; i < 16; ++i) {
            int q = i * TPB + tid;
            if (q < NV4)
                reinterpret_cast<float4*>(sm)[q] =
                    reinterpret_cast<const float4*>(tempJ + gbase)[q];
        }
    } else {
        for (int q = tid; q < TPB * ROW; q += TPB) {
            long long g = gbase + q;
            if (g < total) sm[q] = tempJ[g];
        }
    }
    __syncthreads();

    // extract from template: centered palm points (regs) + bone lengths (smem)
    float sp[5][3];
    if (active) {
        const float t0x = sm[base + 0], t0y = sm[base + 1], t0z = sm[base + 2];
        #pragma unroll
        for (int p = 0; p < 5; ++p) {
            sp[p][0] = sm[base + 3 * PALM5[p] + 0] - t0x;
            sp[p][1] = sm[base + 3 * PALM5[p] + 1] - t0y;
            sp[p][2] = sm[base + 3 * PALM5[p] + 2] - t0z;
        }
        #pragma unroll
        for (int i = 0; i < 15; ++i) {
            float bx = sm[base + 3*CH[i] + 0] - sm[base + 3*PA[i] + 0];
            float by = sm[base + 3*CH[i] + 1] - sm[base + 3*PA[i] + 1];
            float bz = sm[base + 3*CH[i] + 2] - sm[base + 3*PA[i] + 2];
            sblen[bbase + i] = fsqrt_fast(bx*bx + by*by + bz*bz);
        }
    }
    __syncthreads();

    // ================= stage joints (overwrite same buffer) =================
    if (full) {
        #pragma unroll
        for (int i = 0; i < 16; ++i) {
            int q = i * TPB + tid;
            if (q < NV4)
                reinterpret_cast<float4*>(sm)[q] =
                    reinterpret_cast<const float4*>(joints + gbase)[q];
        }
    } else {
        for (int q = tid; q < TPB * ROW; q += TPB) {
            long long g = gbase + q;
            if (g < total) sm[q] = joints[g];
        }
    }
    __syncthreads();

    if (active) {
        const float wx = sm[base + 0], wy = sm[base + 1], wz = sm[base + 2];

        // ---- H = sum_palm src ⊗ dst ----
        float H[3][3] = {{0,0,0},{0,0,0},{0,0,0}};
        #pragma unroll
        for (int p = 0; p < 5; ++p) {
            float jx = sm[base + 3 * PALM5[p] + 0] - wx;
            float jy = sm[base + 3 * PALM5[p] + 1] - wy;
            float jz = sm[base + 3 * PALM5[p] + 2] - wz;
            H[0][0] += sp[p][0]*jx; H[0][1] += sp[p][0]*jy; H[0][2] += sp[p][0]*jz;
            H[1][0] += sp[p][1]*jx; H[1][1] += sp[p][1]*jy; H[1][2] += sp[p][1]*jz;
            H[2][0] += sp[p][2]*jx; H[2][1] += sp[p][2]*jy; H[2][2] += sp[p][2]*jz;
        }

        // ---- A = H^T H ; 3-sweep division-free cyclic Jacobi ----
        float A[3][3];
        #pragma unroll
        for (int a = 0; a < 3; ++a)
            #pragma unroll
            for (int b = 0; b < 3; ++b)
                A[a][b] = H[0][a]*H[0][b] + H[1][a]*H[1][b] + H[2][a]*H[2][b];

        float V[3][3] = {{1,0,0},{0,1,0},{0,0,1}};
        #pragma unroll
        for (int sweep = 0; sweep < 3; ++sweep) {
            #pragma unroll
            for (int pair = 0; pair < 3; ++pair) {
                const int p = (pair == 2) ? 1 : 0;
                const int q = (pair == 0) ? 1 : 2;
                const int r = 3 - p - q;
                float apq = A[p][q];
                float x = 0.5f * (A[q][q] - A[p][p]);
                // inner rotation annihilating apq: tan(2θ) = apq/x, |θ| <= 45°
                float rinv = rsqrtf(x*x + apq*apq + 1e-36f);
                float co = (fabsf(x) + 1e-18f) * rinv;        // cos2θ (>=0)
                float si = apq * copysignf(1.0f, x) * rinv;   // sin2θ = apq·sign(x)/r
                float h  = 0.5f + 0.5f * co;                  // c²
                float cinv = rsqrtf(h);                       // 1/c
                float c = h * cinv;
                float s = 0.5f * si * cinv;
                float t = s * cinv;                           // tanθ
                A[p][p] -= t * apq;
                A[q][q] += t * apq;
                A[p][q] = 0.f; A[q][p] = 0.f;
                float arp = A[r][p], arq = A[r][q];
                A[r][p] = c * arp - s * arq; A[p][r] = A[r][p];
                A[r][q] = s * arp + c * arq; A[q][r] = A[r][q];
                #pragma unroll
                for (int k = 0; k < 3; ++k) {
                    float vp = V[k][p], vq = V[k][q];
                    V[k][p] = c * vp - s * vq;
                    V[k][q] = s * vp + c * vq;
                }
            }
        }

        // sort eigenvalues (descending) -> v1, v2; v3 = v1 x v2
        float e0 = A[0][0], e1 = A[1][1], e2 = A[2][2];
        int i0 = 0; float em = e0;
        if (e1 > em) { i0 = 1; em = e1; }
        if (e2 > em) { i0 = 2; em = e2; }
        const int a1 = (i0 + 1) % 3, b1 = (i0 + 2) % 3;
        float ea = (a1 == 0) ? e0 : (a1 == 1) ? e1 : e2;
        float eb = (b1 == 0) ? e0 : (b1 == 1) ? e1 : e2;
        const int i1 = (ea >= eb) ? a1 : b1;

        float v1[3], v2[3], v3[3];
        #pragma unroll
        for (int k = 0; k < 3; ++k) {
            v1[k] = (i0 == 0) ? V[k][0] : (i0 == 1) ? V[k][1] : V[k][2];
            v2[k] = (i1 == 0) ? V[k][0] : (i1 == 1) ? V[k][1] : V[k][2];
        }
        v3[0] = v1[1]*v2[2] - v1[2]*v2[1];
        v3[1] = v1[2]*v2[0] - v1[0]*v2[2];
        v3[2] = v1[0]*v2[1] - v1[1]*v2[0];

        // u1 = norm(H v1); u2 = norm(GS(H v2)); u3 = u1 x u2
        float u1[3], u2[3], u3[3];
        #pragma unroll
        for (int k = 0; k < 3; ++k)
            u1[k] = H[k][0]*v1[0] + H[k][1]*v1[1] + H[k][2]*v1[2];
        {
            float inv = rsqrtf(u1[0]*u1[0] + u1[1]*u1[1] + u1[2]*u1[2] + 1e-30f);
            u1[0] *= inv; u1[1] *= inv; u1[2] *= inv;
        }
        #pragma unroll
        for (int k = 0; k < 3; ++k)
            u2[k] = H[k][0]*v2[0] + H[k][1]*v2[1] + H[k][2]*v2[2];
        {
            float pr = u1[0]*u2[0] + u1[1]*u2[1] + u1[2]*u2[2];
            u2[0] -= pr * u1[0]; u2[1] -= pr * u1[1]; u2[2] -= pr * u1[2];
            float inv = rsqrtf(u2[0]*u2[0] + u2[1]*u2[1] + u2[2]*u2[2] + 1e-30f);
            u2[0] *= inv; u2[1] *= inv; u2[2] *= inv;
        }
        u3[0] = u1[1]*u2[2] - u1[2]*u2[1];
        u3[1] = u1[2]*u2[0] - u1[0]*u2[2];
        u3[2] = u1[0]*u2[1] - u1[1]*u2[0];

        // R = v1 u1^T + v2 u2^T + v3 u3^T
        float R[3][3];
        #pragma unroll
        for (int a = 0; a < 3; ++a)
            #pragma unroll
            for (int b = 0; b < 3; ++b)
                R[a][b] = v1[a]*u1[b] + v2[a]*u2[b] + v3[a]*u3[b];

        // ---- rotate template palm points, write palm outputs in place ----
        #pragma unroll
        for (int p = 0; p < 5; ++p) {
            float tx = R[0][0]*sp[p][0] + R[0][1]*sp[p][1] + R[0][2]*sp[p][2];
            float ty = R[1][0]*sp[p][0] + R[1][1]*sp[p][1] + R[1][2]*sp[p][2];
            float tz = R[2][0]*sp[p][0] + R[2][1]*sp[p][1] + R[2][2]*sp[p][2];
            sm[base + 3*PALM5[p] + 0] = tx + wx;
            sm[base + 3*PALM5[p] + 1] = ty + wy;
            sm[base + 3*PALM5[p] + 2] = tz + wz;
        }
        // wrist slot already holds w (T[0] = 0)

        // ---- kinematic chain, finger-major; closed-form clamp (1 MUFU/step) ----
        // flex (c1<0): n = blen * rsqrt(v0sq*s2') * (v0sq*v1 - c1*v0),
        //              s2' = v0sq*d2 - c1^2 (Lagrange), |n| = blen exactly.
        // no-flex:     n = blen * rsqrt(d2) * v1.
        #pragma unroll
        for (int f = 0; f < 5; ++f) {
            float gx = 0.f, gy = 0.f, gz = 0.f;
            float px = sm[base + 3*PALM5[f] + 0] - wx;
            float py = sm[base + 3*PALM5[f] + 1] - wy;
            float pz = sm[base + 3*PALM5[f] + 2] - wz;
            #pragma unroll
            for (int k = 0; k < 3; ++k) {
                const int i = 3 * f + k;
                const int ch = CH[i];
                const float bl = sblen[bbase + i];

                float v1x = (sm[base + 3*ch + 0] - wx) - px;
                float v1y = (sm[base + 3*ch + 1] - wy) - py;
                float v1z = (sm[base + 3*ch + 2] - wz) - pz;
                float v0x = px - gx, v0y = py - gy, v0z = pz - gz;

                float d2   = v1x*v1x + v1y*v1y + v1z*v1z;
                float c1   = v0x*v1x + v0y*v1y + v0z*v1z;
                float v0sq = v0x*v0x + v0y*v0y + v0z*v0z;

                bool flex = (c1 < 0.0f);
                float s2p = fmaxf(v0sq * d2 - c1 * c1, 0.0f);

                float arg = flex ? v0sq * s2p : d2;
                float w   = bl * rsqrtf(arg + 1e-30f);
                float mx  = flex ? v0sq * v1x - c1 * v0x : v1x;
                float my  = flex ? v0sq * v1y - c1 * v0y : v1y;
                float mz  = flex ? v0sq * v1z - c1 * v0z : v1z;

                float cx = px + w * mx;
                float cy = py + w * my;
                float cz = pz + w * mz;

                // child's raw joint value is dead now -> write output in place
                sm[base + 3*ch + 0] = cx + wx;
                sm[base + 3*ch + 1] = cy + wy;
                sm[base + 3*ch + 2] = cz + wz;

                gx = px; gy = py; gz = pz;
                px = cx; py = cy; pz = cz;
            }
        }
    }
    __syncthreads();

    // ================= coalesced float4 store =================
    if (full) {
        #pragma unroll
        for (int i = 0; i < 16; ++i) {
            int q = i * TPB + tid;
            if (q < NV4)
                reinterpret_cast<float4*>(out + gbase)[q] =
                    reinterpret_cast<const float4*>(sm)[q];
        }
    } else {
        for (int q = tid; q < TPB * ROW; q += TPB) {
            long long g = gbase + q;
            if (g < total) out[g] = sm[q];
        }
    }
}

extern "C" void kernel_launch(void* const* d_in, const int* in_sizes, int n_in,
                              void* d_out, int out_size)
{
    const float* joints = (const float*)d_in[0];
    const float* tempJ  = (const float*)d_in[1];
    float* out = (float*)d_out;
    const int n = in_sizes[0] / ROW;     // 131072
    const int blocks = (n + TPB - 1) / TPB;
    kin_kernel<<<blocks, TPB>>>(joints, tempJ, out, n);
}